// round 7
// baseline (speedup 1.0000x reference)
#include <cuda_runtime.h>
#include <cstddef>

#define NN   8192
#define FIN  512
#define HID  128
#define NCLS 16
#define CAP  256

static __device__ __constant__ float C_RES  = 0.5555555555555556f;  // 1/(1+0.8)
static __device__ __constant__ float C_PROP = 0.4444444444444444f;  // 0.8/(1+0.8)

// ---- scratch (device globals; no allocation allowed) ----
__device__ int   g_col[NN * CAP];
__device__ float g_val[NN * CAP];
__device__ int   g_cnt[NN];
__device__ float g_dinv[NN];
__device__ float g_h1[NN * HID];
__device__ float g_bufA[NN * HID];
__device__ float g_bufB[NN * HID];
__device__ float g_h2[NN * NCLS];
__device__ float g_cA[NN * NCLS];
__device__ float g_cB[NN * NCLS];

// ---------------------------------------------------------------------------
// 1) Fused front kernel (block specialization):
//    blocks [0, 2048)  : extract CSR of (A+I), 4 warps/block, float4 loads
//    blocks [2048,2560): h1 = x @ W1 tile (16 rows x 128 cols), float4 LDS
//    The two halves are independent; DRAM-bound extract overlaps FMA-bound GEMM.
// ---------------------------------------------------------------------------
__global__ __launch_bounds__(128) void k_front(const float* __restrict__ adj,
                                               const float* __restrict__ x,
                                               const float* __restrict__ W1) {
    __shared__ float xs[16 * FIN];   // only used by the GEMM branch (32 KB)
    int bid = blockIdx.x;
    if (bid < 2048) {
        // ---- extract branch: one warp per row ----
        int row  = bid * 4 + (threadIdx.x >> 5);
        int lane = threadIdx.x & 31;
        const float4* row4 = (const float4*)(adj + (size_t)row * NN);
        int base = row * CAP;
        int cnt = 0;
        float deg = 0.0f;
        for (int c0 = 0; c0 < NN; c0 += 128) {
            float4 v = __ldcs(&row4[(c0 >> 2) + lane]);
            int cb = c0 + 4 * lane;
            float v0 = v.x, v1 = v.y, v2 = v.z, v3 = v.w;
            if (cb + 0 == row) v0 += 1.0f;   // self loop
            if (cb + 1 == row) v1 += 1.0f;
            if (cb + 2 == row) v2 += 1.0f;
            if (cb + 3 == row) v3 += 1.0f;
            deg += (v0 + v1) + (v2 + v3);
            unsigned lt = (1u << lane) - 1u;
            unsigned m;
            m = __ballot_sync(0xffffffffu, v0 != 0.0f);
            if (v0 != 0.0f) { int p = base + cnt + __popc(m & lt);
                if (p < base + CAP) { g_col[p] = cb + 0; g_val[p] = v0; } }
            cnt += __popc(m);
            m = __ballot_sync(0xffffffffu, v1 != 0.0f);
            if (v1 != 0.0f) { int p = base + cnt + __popc(m & lt);
                if (p < base + CAP) { g_col[p] = cb + 1; g_val[p] = v1; } }
            cnt += __popc(m);
            m = __ballot_sync(0xffffffffu, v2 != 0.0f);
            if (v2 != 0.0f) { int p = base + cnt + __popc(m & lt);
                if (p < base + CAP) { g_col[p] = cb + 2; g_val[p] = v2; } }
            cnt += __popc(m);
            m = __ballot_sync(0xffffffffu, v3 != 0.0f);
            if (v3 != 0.0f) { int p = base + cnt + __popc(m & lt);
                if (p < base + CAP) { g_col[p] = cb + 3; g_val[p] = v3; } }
            cnt += __popc(m);
        }
#pragma unroll
        for (int o = 16; o > 0; o >>= 1) deg += __shfl_xor_sync(0xffffffffu, deg, o);
        if (lane == 0) {
            g_cnt[row]  = cnt < CAP ? cnt : CAP;
            g_dinv[row] = rsqrtf(deg);    // deg >= 1 (self loop)
        }
    } else {
        // ---- GEMM branch: 16 rows x 128 cols per block ----
        int r0 = (bid - 2048) * 16;
        int f  = threadIdx.x;   // 0..127: output column
        const float4* srcv = (const float4*)(x + (size_t)r0 * FIN);
        float4* dstv = (float4*)xs;
        for (int t = f; t < 16 * FIN / 4; t += 128) dstv[t] = srcv[t];
        __syncthreads();
        float acc[16];
#pragma unroll
        for (int r = 0; r < 16; r++) acc[r] = 0.0f;
        for (int k = 0; k < FIN; k += 4) {
            float w0 = __ldg(&W1[(k + 0) * HID + f]);
            float w1 = __ldg(&W1[(k + 1) * HID + f]);
            float w2 = __ldg(&W1[(k + 2) * HID + f]);
            float w3 = __ldg(&W1[(k + 3) * HID + f]);
#pragma unroll
            for (int r = 0; r < 16; r++) {
                float4 xv = *(const float4*)&xs[r * FIN + k];
                acc[r] = fmaf(xv.x, w0, acc[r]);
                acc[r] = fmaf(xv.y, w1, acc[r]);
                acc[r] = fmaf(xv.z, w2, acc[r]);
                acc[r] = fmaf(xv.w, w3, acc[r]);
            }
        }
#pragma unroll
        for (int r = 0; r < 16; r++) g_h1[(size_t)(r0 + r) * HID + f] = acc[r];
    }
}

// ---------------------------------------------------------------------------
// 2) val(i,j) *= dinv[i]*dinv[j]
// ---------------------------------------------------------------------------
__global__ __launch_bounds__(64) void k_scale() {
    int i = blockIdx.x;
    int cnt = g_cnt[i];
    float di = g_dinv[i];
    int base = i * CAP;
    for (int t = threadIdx.x; t < cnt; t += 64) {
        g_val[base + t] *= di * g_dinv[g_col[base + t]];
    }
}

// ---------------------------------------------------------------------------
// 3) SpMM width 128: one warp per row, float4 per lane, int4/float4 edge loads
// ---------------------------------------------------------------------------
__global__ __launch_bounds__(256) void k_spmm128(int s) {
    int row  = blockIdx.x * 8 + (threadIdx.x >> 5);
    int lane = threadIdx.x & 31;
    const float4* src = (const float4*)((s == 0) ? g_h1 : ((s & 1) ? g_bufA : g_bufB));
    float4* dst = (float4*)((s & 1) ? g_bufB : g_bufA);
    int cnt = g_cnt[row];
    int base = row * CAP;
    float ax = 0.f, ay = 0.f, az = 0.f, aw = 0.f;
    int k = 0;
    for (; k + 4 <= cnt; k += 4) {
        int4   cc = __ldg((const int4*)&g_col[base + k]);      // base%256==0, k%4==0
        float4 vv = __ldg((const float4*)&g_val[base + k]);
        float4 d0 = __ldg(&src[(size_t)cc.x * 32 + lane]);
        float4 d1 = __ldg(&src[(size_t)cc.y * 32 + lane]);
        float4 d2 = __ldg(&src[(size_t)cc.z * 32 + lane]);
        float4 d3 = __ldg(&src[(size_t)cc.w * 32 + lane]);
        ax = fmaf(vv.x, d0.x, ax); ay = fmaf(vv.x, d0.y, ay);
        az = fmaf(vv.x, d0.z, az); aw = fmaf(vv.x, d0.w, aw);
        ax = fmaf(vv.y, d1.x, ax); ay = fmaf(vv.y, d1.y, ay);
        az = fmaf(vv.y, d1.z, az); aw = fmaf(vv.y, d1.w, aw);
        ax = fmaf(vv.z, d2.x, ax); ay = fmaf(vv.z, d2.y, ay);
        az = fmaf(vv.z, d2.z, az); aw = fmaf(vv.z, d2.w, aw);
        ax = fmaf(vv.w, d3.x, ax); ay = fmaf(vv.w, d3.y, ay);
        az = fmaf(vv.w, d3.z, az); aw = fmaf(vv.w, d3.w, aw);
    }
    for (; k < cnt; k++) {
        int   c = __ldg(&g_col[base + k]);
        float v = __ldg(&g_val[base + k]);
        float4 d = __ldg(&src[(size_t)c * 32 + lane]);
        ax = fmaf(v, d.x, ax); ay = fmaf(v, d.y, ay);
        az = fmaf(v, d.z, az); aw = fmaf(v, d.w, aw);
    }
    float4 h = ((const float4*)g_h1)[(size_t)row * 32 + lane];
    float4 o;
    o.x = C_PROP * ax + C_RES * h.x;
    o.y = C_PROP * ay + C_RES * h.y;
    o.z = C_PROP * az + C_RES * h.z;
    o.w = C_PROP * aw + C_RES * h.w;
    dst[(size_t)row * 32 + lane] = o;
}

// ---------------------------------------------------------------------------
// 4) h2 = relu(diffused1 + b1) @ W2
// ---------------------------------------------------------------------------
__global__ __launch_bounds__(128) void k_gemm2(const float* __restrict__ W2,
                                               const float* __restrict__ b1) {
    int idx = blockIdx.x * blockDim.x + threadIdx.x;   // 0..131071
    int row = idx >> 4;
    int c   = idx & 15;
    const float* src = g_bufB + (size_t)row * HID;     // 8 steps end in bufB
    float acc = 0.0f;
#pragma unroll 8
    for (int k = 0; k < HID; k++) {
        float hv = fmaxf(src[k] + __ldg(&b1[k]), 0.0f);
        acc = fmaf(hv, __ldg(&W2[k * NCLS + c]), acc);
    }
    g_h2[idx] = acc;
}

// ---------------------------------------------------------------------------
// 5) SpMM width 16: one warp per row; lane = (edge_group 0..7, quarter 0..3).
//    Butterfly reduce over edge groups. Step 7 fuses bias + log_softmax.
// ---------------------------------------------------------------------------
__global__ __launch_bounds__(256) void k_spmm16(int s, const float* __restrict__ b2,
                                                float* __restrict__ out) {
    int row  = blockIdx.x * 8 + (threadIdx.x >> 5);
    int lane = threadIdx.x & 31;
    int eg = lane >> 2;      // edge group 0..7
    int q  = lane & 3;       // quarter (4 floats)
    const float4* src = (const float4*)((s == 0) ? g_h2 : ((s & 1) ? g_cA : g_cB));
    float4* dst = (float4*)((s & 1) ? g_cB : g_cA);
    int cnt = g_cnt[row];
    int base = row * CAP;
    float ax = 0.f, ay = 0.f, az = 0.f, aw = 0.f;
    for (int k = eg; k < cnt; k += 8) {
        int   c = __ldg(&g_col[base + k]);
        float v = __ldg(&g_val[base + k]);
        float4 d = __ldg(&src[(size_t)c * 4 + q]);
        ax = fmaf(v, d.x, ax); ay = fmaf(v, d.y, ay);
        az = fmaf(v, d.z, az); aw = fmaf(v, d.w, aw);
    }
    // butterfly over edge groups (lanes differing in bits 2..4); all lanes end
    // with the full quarter-q sum
#pragma unroll
    for (int o = 4; o <= 16; o <<= 1) {
        ax += __shfl_xor_sync(0xffffffffu, ax, o);
        ay += __shfl_xor_sync(0xffffffffu, ay, o);
        az += __shfl_xor_sync(0xffffffffu, az, o);
        aw += __shfl_xor_sync(0xffffffffu, aw, o);
    }
    float4 h = ((const float4*)g_h2)[(size_t)row * 4 + q];
    float4 o4;
    o4.x = C_PROP * ax + C_RES * h.x;
    o4.y = C_PROP * ay + C_RES * h.y;
    o4.z = C_PROP * az + C_RES * h.z;
    o4.w = C_PROP * aw + C_RES * h.w;
    if (s < 7) {
        if (eg == 0) dst[(size_t)row * 4 + q] = o4;
    } else {
        // fused: v = o4 + b2; log_softmax over the 16 classes
        o4.x += __ldg(&b2[q * 4 + 0]);
        o4.y += __ldg(&b2[q * 4 + 1]);
        o4.z += __ldg(&b2[q * 4 + 2]);
        o4.w += __ldg(&b2[q * 4 + 3]);
        float mx = fmaxf(fmaxf(o4.x, o4.y), fmaxf(o4.z, o4.w));
#pragma unroll
        for (int o = 1; o <= 2; o <<= 1) mx = fmaxf(mx, __shfl_xor_sync(0xffffffffu, mx, o));
        float se = expf(o4.x - mx) + expf(o4.y - mx) + expf(o4.z - mx) + expf(o4.w - mx);
#pragma unroll
        for (int o = 1; o <= 2; o <<= 1) se += __shfl_xor_sync(0xffffffffu, se, o);
        float lse = mx + logf(se);
        if (eg == 0) {
            float4 r;
            r.x = o4.x - lse; r.y = o4.y - lse; r.z = o4.z - lse; r.w = o4.w - lse;
            ((float4*)out)[(size_t)row * 4 + q] = r;
        }
    }
}

// ---------------------------------------------------------------------------
extern "C" void kernel_launch(void* const* d_in, const int* in_sizes, int n_in,
                              void* d_out, int out_size) {
    const float* x   = (const float*)d_in[0];
    const float* adj = (const float*)d_in[1];
    const float* W1  = (const float*)d_in[2];
    const float* b1  = (const float*)d_in[3];
    const float* W2  = (const float*)d_in[4];
    const float* b2  = (const float*)d_in[5];
    float* out = (float*)d_out;

    k_front<<<2048 + NN / 16, 128>>>(adj, x, W1);        // extract + gemm1 overlapped
    k_scale<<<NN, 64>>>();
    for (int s = 0; s < 8; s++) k_spmm128<<<NN / 8, 256>>>(s);
    k_gemm2<<<(NN * NCLS) / 128, 128>>>(W2, b1);
    for (int s = 0; s < 8; s++) k_spmm16<<<NN / 8, 256>>>(s, b2, out);
}

// round 9
// speedup vs baseline: 1.7023x; 1.7023x over previous
#include <cuda_runtime.h>
#include <cstddef>

#define NN   8192
#define FIN  512
#define HID  128
#define NCLS 16
#define CAP  256

static __device__ __constant__ float C_RES  = 0.5555555555555556f;  // 1/(1+0.8)
static __device__ __constant__ float C_PROP = 0.4444444444444444f;  // 0.8/(1+0.8)

// ---- scratch (device globals; no allocation allowed) ----
__device__ int   g_col[NN * CAP];
__device__ float g_val[NN * CAP];
__device__ int   g_cnt[NN];
__device__ float g_dinv[NN];
__device__ float g_h1[NN * HID];
__device__ float g_bufA[NN * HID];
__device__ float g_bufB[NN * HID];
__device__ float g_h2[NN * NCLS];
__device__ float g_cA[NN * NCLS];
__device__ float g_cB[NN * NCLS];

// ---------------------------------------------------------------------------
// 1) Fused front kernel (block specialization):
//    blocks [0, 2048)  : extract CSR of (A+I), 4 warps/block, float4 loads
//    blocks [2048,2560): h1 = x @ W1 tile (16 rows x 128 cols), float4 LDS
// ---------------------------------------------------------------------------
__global__ __launch_bounds__(128) void k_front(const float* __restrict__ adj,
                                               const float* __restrict__ x,
                                               const float* __restrict__ W1) {
    __shared__ float xs[16 * FIN];   // only used by the GEMM branch (32 KB)
    int bid = blockIdx.x;
    if (bid < 2048) {
        // ---- extract branch: one warp per row ----
        int row  = bid * 4 + (threadIdx.x >> 5);
        int lane = threadIdx.x & 31;
        const float4* row4 = (const float4*)(adj + (size_t)row * NN);
        int base = row * CAP;
        int cnt = 0;
        float deg = 0.0f;
        for (int c0 = 0; c0 < NN; c0 += 128) {
            float4 v = __ldcs(&row4[(c0 >> 2) + lane]);
            int cb = c0 + 4 * lane;
            float v0 = v.x, v1 = v.y, v2 = v.z, v3 = v.w;
            if (cb + 0 == row) v0 += 1.0f;   // self loop
            if (cb + 1 == row) v1 += 1.0f;
            if (cb + 2 == row) v2 += 1.0f;
            if (cb + 3 == row) v3 += 1.0f;
            deg += (v0 + v1) + (v2 + v3);
            unsigned lt = (1u << lane) - 1u;
            unsigned m;
            m = __ballot_sync(0xffffffffu, v0 != 0.0f);
            if (v0 != 0.0f) { int p = base + cnt + __popc(m & lt);
                if (p < base + CAP) { g_col[p] = cb + 0; g_val[p] = v0; } }
            cnt += __popc(m);
            m = __ballot_sync(0xffffffffu, v1 != 0.0f);
            if (v1 != 0.0f) { int p = base + cnt + __popc(m & lt);
                if (p < base + CAP) { g_col[p] = cb + 1; g_val[p] = v1; } }
            cnt += __popc(m);
            m = __ballot_sync(0xffffffffu, v2 != 0.0f);
            if (v2 != 0.0f) { int p = base + cnt + __popc(m & lt);
                if (p < base + CAP) { g_col[p] = cb + 2; g_val[p] = v2; } }
            cnt += __popc(m);
            m = __ballot_sync(0xffffffffu, v3 != 0.0f);
            if (v3 != 0.0f) { int p = base + cnt + __popc(m & lt);
                if (p < base + CAP) { g_col[p] = cb + 3; g_val[p] = v3; } }
            cnt += __popc(m);
        }
#pragma unroll
        for (int o = 16; o > 0; o >>= 1) deg += __shfl_xor_sync(0xffffffffu, deg, o);
        if (lane == 0) {
            g_cnt[row]  = cnt < CAP ? cnt : CAP;
            g_dinv[row] = rsqrtf(deg);    // deg >= 1 (self loop)
        }
    } else {
        // ---- GEMM branch: 16 rows x 128 cols per block ----
        int r0 = (bid - 2048) * 16;
        int f  = threadIdx.x;   // 0..127: output column
        const float4* srcv = (const float4*)(x + (size_t)r0 * FIN);
        float4* dstv = (float4*)xs;
        for (int t = f; t < 16 * FIN / 4; t += 128) dstv[t] = srcv[t];
        __syncthreads();
        float acc[16];
#pragma unroll
        for (int r = 0; r < 16; r++) acc[r] = 0.0f;
        for (int k = 0; k < FIN; k += 4) {
            float w0 = __ldg(&W1[(k + 0) * HID + f]);
            float w1 = __ldg(&W1[(k + 1) * HID + f]);
            float w2 = __ldg(&W1[(k + 2) * HID + f]);
            float w3 = __ldg(&W1[(k + 3) * HID + f]);
#pragma unroll
            for (int r = 0; r < 16; r++) {
                float4 xv = *(const float4*)&xs[r * FIN + k];
                acc[r] = fmaf(xv.x, w0, acc[r]);
                acc[r] = fmaf(xv.y, w1, acc[r]);
                acc[r] = fmaf(xv.z, w2, acc[r]);
                acc[r] = fmaf(xv.w, w3, acc[r]);
            }
        }
#pragma unroll
        for (int r = 0; r < 16; r++) g_h1[(size_t)(r0 + r) * HID + f] = acc[r];
    }
}

// ---------------------------------------------------------------------------
// 2) val(i,j) *= dinv[i]*dinv[j]
// ---------------------------------------------------------------------------
__global__ __launch_bounds__(64) void k_scale() {
    int i = blockIdx.x;
    int cnt = g_cnt[i];
    float di = g_dinv[i];
    int base = i * CAP;
    for (int t = threadIdx.x; t < cnt; t += 64) {
        g_val[base + t] *= di * g_dinv[g_col[base + t]];
    }
}

// ---------------------------------------------------------------------------
// 3) SpMM width 128: one warp per row, float4 per lane (512B coalesced gathers)
//    EXACT round-5 body (measured 20.6us/step, regs=32, occ=71.5%).
// ---------------------------------------------------------------------------
__global__ __launch_bounds__(256) void k_spmm128(int s) {
    int row  = blockIdx.x * 8 + (threadIdx.x >> 5);
    int lane = threadIdx.x & 31;
    const float4* src = (const float4*)((s == 0) ? g_h1 : ((s & 1) ? g_bufA : g_bufB));
    float4* dst = (float4*)((s & 1) ? g_bufB : g_bufA);
    int cnt = g_cnt[row];
    int base = row * CAP;
    float ax = 0.f, ay = 0.f, az = 0.f, aw = 0.f;
    int k = 0;
    for (; k + 4 <= cnt; k += 4) {
#pragma unroll
        for (int u = 0; u < 4; u++) {
            int   c = __ldg(&g_col[base + k + u]);
            float v = __ldg(&g_val[base + k + u]);
            float4 d = src[(size_t)c * 32 + lane];
            ax = fmaf(v, d.x, ax); ay = fmaf(v, d.y, ay);
            az = fmaf(v, d.z, az); aw = fmaf(v, d.w, aw);
        }
    }
    for (; k < cnt; k++) {
        int   c = __ldg(&g_col[base + k]);
        float v = __ldg(&g_val[base + k]);
        float4 d = src[(size_t)c * 32 + lane];
        ax = fmaf(v, d.x, ax); ay = fmaf(v, d.y, ay);
        az = fmaf(v, d.z, az); aw = fmaf(v, d.w, aw);
    }
    float4 h = ((const float4*)g_h1)[(size_t)row * 32 + lane];
    float4 o;
    o.x = C_PROP * ax + C_RES * h.x;
    o.y = C_PROP * ay + C_RES * h.y;
    o.z = C_PROP * az + C_RES * h.z;
    o.w = C_PROP * aw + C_RES * h.w;
    dst[(size_t)row * 32 + lane] = o;
}

// ---------------------------------------------------------------------------
// 4) h2 = relu(diffused1 + b1) @ W2
// ---------------------------------------------------------------------------
__global__ __launch_bounds__(128) void k_gemm2(const float* __restrict__ W2,
                                               const float* __restrict__ b1) {
    int idx = blockIdx.x * blockDim.x + threadIdx.x;   // 0..131071
    int row = idx >> 4;
    int c   = idx & 15;
    const float* src = g_bufB + (size_t)row * HID;     // 8 steps end in bufB
    float acc = 0.0f;
#pragma unroll 8
    for (int k = 0; k < HID; k++) {
        float hv = fmaxf(src[k] + __ldg(&b1[k]), 0.0f);
        acc = fmaf(hv, __ldg(&W2[k * NCLS + c]), acc);
    }
    g_h2[idx] = acc;
}

// ---------------------------------------------------------------------------
// 5) SpMM width 16: one warp per row; lane = (edge_group 0..7, quarter 0..3).
//    Butterfly reduce over edge groups. Step 7 fuses bias + log_softmax.
// ---------------------------------------------------------------------------
__global__ __launch_bounds__(256) void k_spmm16(int s, const float* __restrict__ b2,
                                                float* __restrict__ out) {
    int row  = blockIdx.x * 8 + (threadIdx.x >> 5);
    int lane = threadIdx.x & 31;
    int eg = lane >> 2;      // edge group 0..7
    int q  = lane & 3;       // quarter (4 floats)
    const float4* src = (const float4*)((s == 0) ? g_h2 : ((s & 1) ? g_cA : g_cB));
    float4* dst = (float4*)((s & 1) ? g_cB : g_cA);
    int cnt = g_cnt[row];
    int base = row * CAP;
    float ax = 0.f, ay = 0.f, az = 0.f, aw = 0.f;
    for (int k = eg; k < cnt; k += 8) {
        int   c = __ldg(&g_col[base + k]);
        float v = __ldg(&g_val[base + k]);
        float4 d = __ldg(&src[(size_t)c * 4 + q]);
        ax = fmaf(v, d.x, ax); ay = fmaf(v, d.y, ay);
        az = fmaf(v, d.z, az); aw = fmaf(v, d.w, aw);
    }
    // butterfly over edge groups (lanes differing in bits 2..4)
#pragma unroll
    for (int o = 4; o <= 16; o <<= 1) {
        ax += __shfl_xor_sync(0xffffffffu, ax, o);
        ay += __shfl_xor_sync(0xffffffffu, ay, o);
        az += __shfl_xor_sync(0xffffffffu, az, o);
        aw += __shfl_xor_sync(0xffffffffu, aw, o);
    }
    float4 h = ((const float4*)g_h2)[(size_t)row * 4 + q];
    float4 o4;
    o4.x = C_PROP * ax + C_RES * h.x;
    o4.y = C_PROP * ay + C_RES * h.y;
    o4.z = C_PROP * az + C_RES * h.z;
    o4.w = C_PROP * aw + C_RES * h.w;
    if (s < 7) {
        if (eg == 0) dst[(size_t)row * 4 + q] = o4;
    } else {
        // fused: v = o4 + b2; log_softmax over the 16 classes
        o4.x += __ldg(&b2[q * 4 + 0]);
        o4.y += __ldg(&b2[q * 4 + 1]);
        o4.z += __ldg(&b2[q * 4 + 2]);
        o4.w += __ldg(&b2[q * 4 + 3]);
        float mx = fmaxf(fmaxf(o4.x, o4.y), fmaxf(o4.z, o4.w));
#pragma unroll
        for (int o = 1; o <= 2; o <<= 1) mx = fmaxf(mx, __shfl_xor_sync(0xffffffffu, mx, o));
        float se = expf(o4.x - mx) + expf(o4.y - mx) + expf(o4.z - mx) + expf(o4.w - mx);
#pragma unroll
        for (int o = 1; o <= 2; o <<= 1) se += __shfl_xor_sync(0xffffffffu, se, o);
        float lse = mx + logf(se);
        if (eg == 0) {
            float4 r;
            r.x = o4.x - lse; r.y = o4.y - lse; r.z = o4.z - lse; r.w = o4.w - lse;
            ((float4*)out)[(size_t)row * 4 + q] = r;
        }
    }
}

// ---------------------------------------------------------------------------
extern "C" void kernel_launch(void* const* d_in, const int* in_sizes, int n_in,
                              void* d_out, int out_size) {
    const float* x   = (const float*)d_in[0];
    const float* adj = (const float*)d_in[1];
    const float* W1  = (const float*)d_in[2];
    const float* b1  = (const float*)d_in[3];
    const float* W2  = (const float*)d_in[4];
    const float* b2  = (const float*)d_in[5];
    float* out = (float*)d_out;

    k_front<<<2048 + NN / 16, 128>>>(adj, x, W1);        // extract + gemm1 overlapped
    k_scale<<<NN, 64>>>();
    for (int s = 0; s < 8; s++) k_spmm128<<<NN / 8, 256>>>(s);
    k_gemm2<<<(NN * NCLS) / 128, 128>>>(W2, b1);
    for (int s = 0; s < 8; s++) k_spmm16<<<NN / 8, 256>>>(s, b2, out);
}